// round 12
// baseline (speedup 1.0000x reference)
#include <cuda_runtime.h>
#include <math.h>

// ---------------- problem constants ----------------
#define NTOT   22743
#define N0     1083
#define N1     4332
#define N2     17328
#define OFF1   1083
#define OFF2   5415
#define BATCH  8
#define TOPK   1000
#define NCAND  3000
#define MAXDET 100
#define IMGMAX 607
#define SORTN  4096
#define CH     512
#define CW     16
#define MIN_SC 0.05f

#define NBAR(id, cnt) asm volatile("bar.sync %0, %1;" :: "r"(id), "r"(cnt) : "memory")

// ---------------- device scratch ----------------
__device__ float g_score[BATCH * NTOT];
__device__ int   g_cls[BATCH * NTOT];

__device__ __forceinline__ float sigm(float x) { return 1.0f / (1.0f + expf(-x)); }

// ---------------- stage 1: decode scores only (4 threads / anchor) ----------------
__global__ void decode_kernel(
    const float* __restrict__ obj0, const float* __restrict__ cls0,
    const float* __restrict__ obj1, const float* __restrict__ cls1,
    const float* __restrict__ obj2, const float* __restrict__ cls2)
{
    int t = blockIdx.x * blockDim.x + threadIdx.x;
    int a = t >> 2;
    int sub = t & 3;
    if (a >= BATCH * NTOT) a = BATCH * NTOT - 1;   // duplicates write identical data
    int b = a / NTOT;
    int n = a - b * NTOT;

    const float *obj, *cls;
    int local, cnt;
    if (n < N0)        { obj = obj0; cls = cls0; local = n;        cnt = N0; }
    else if (n < OFF2) { obj = obj1; cls = cls1; local = n - OFF1; cnt = N1; }
    else               { obj = obj2; cls = cls2; local = n - OFF2; cnt = N2; }

    size_t base = (size_t)b * cnt + local;

    const float4* cp4 = reinterpret_cast<const float4*>(cls + base * 80) + sub * 5;
    float v[20];
    {
        float4 q0 = __ldg(cp4);
        float4 q1 = __ldg(cp4 + 1);
        float4 q2 = __ldg(cp4 + 2);
        float4 q3 = __ldg(cp4 + 3);
        float4 q4 = __ldg(cp4 + 4);
        v[0]=q0.x; v[1]=q0.y; v[2]=q0.z; v[3]=q0.w;
        v[4]=q1.x; v[5]=q1.y; v[6]=q1.z; v[7]=q1.w;
        v[8]=q2.x; v[9]=q2.y; v[10]=q2.z; v[11]=q2.w;
        v[12]=q3.x; v[13]=q3.y; v[14]=q3.z; v[15]=q3.w;
        v[16]=q4.x; v[17]=q4.y; v[18]=q4.z; v[19]=q4.w;
    }
    float m01 = fmaxf(v[0], v[1]),   m23 = fmaxf(v[2], v[3]);
    float m45 = fmaxf(v[4], v[5]),   m67 = fmaxf(v[6], v[7]);
    float m89 = fmaxf(v[8], v[9]),   mAB = fmaxf(v[10], v[11]);
    float mCD = fmaxf(v[12], v[13]), mEF = fmaxf(v[14], v[15]);
    float mGH = fmaxf(v[16], v[17]), mIJ = fmaxf(v[18], v[19]);
    float a0 = fmaxf(m01, m23), a1 = fmaxf(m45, m67), a2 = fmaxf(m89, mAB);
    float a3 = fmaxf(mCD, mEF), a4 = fmaxf(mGH, mIJ);
    float best = fmaxf(fmaxf(fmaxf(a0, a1), fmaxf(a2, a3)), a4);
    int bi = 19;
#pragma unroll
    for (int j = 18; j >= 0; --j) bi = (v[j] == best) ? j : bi;
    bi += sub * 20;

#pragma unroll
    for (int off = 1; off <= 2; off <<= 1) {
        float ov = __shfl_xor_sync(0xffffffffu, best, off);
        int   oi = __shfl_xor_sync(0xffffffffu, bi, off);
        if (ov > best || (ov == best && oi < bi)) { best = ov; bi = oi; }
    }

    if (sub == 0) {
        float o = sigm(__ldg(obj + base));
        g_score[a] = sigm(best) * o;
        g_cls[a]   = bi;
    }
}

// ---------------- stage 2: fused topk + sort + matrix-free NMS ----------------
#define DSMEM 32768   // u64 keys[4096] / sort workspace

__device__ __forceinline__ unsigned long long u64max(unsigned long long a, unsigned long long b) { return a > b ? a : b; }
__device__ __forceinline__ unsigned long long u64min(unsigned long long a, unsigned long long b) { return a < b ? a : b; }
__device__ __forceinline__ void cswap(unsigned long long& a, unsigned long long& b, bool desc)
{
    if (desc ? (a < b) : (a > b)) { unsigned long long t = a; a = b; b = t; }
}

__global__ void __launch_bounds__(1024) topk_sortnms_kernel(
    const float* __restrict__ reg0, const float* __restrict__ anc0,
    const float* __restrict__ reg1, const float* __restrict__ anc1,
    const float* __restrict__ reg2, const float* __restrict__ anc2,
    float* __restrict__ out)
{
    int b = blockIdx.x;
    int tid = threadIdx.x;
    int lane = tid & 31, gw = tid >> 5;

    extern __shared__ __align__(16) unsigned char dsm[];
    unsigned long long* keys = reinterpret_cast<unsigned long long*>(dsm);  // [4096]
    unsigned long long* sk   = keys;                                        // sort ws

    __shared__ unsigned red1[32], red2[32], red3[32];
    __shared__ unsigned sLo[3], sHi[3], sF[3];
    __shared__ unsigned long long ckey[CH];
    __shared__ int cx1[CH], cy1[CH], cx2[CH], cy2[CH], car[CH];
    __shared__ unsigned supv[CW], limw[CW];
    __shared__ int kp1[MAXDET], kp2[MAXDET], kar2[MAXDET], kn[MAXDET];
    __shared__ float ksc[MAXDET];
    __shared__ int s_kept, s_done;

    if (tid == 0) { s_kept = 0; s_done = 0; }
    for (int idx = 3000 + tid; idx < SORTN; idx += 1024) keys[idx] = 0ull;

    // ======== PHASE A: per-level top-1000, warp-specialized partitions ========
    int L, pbw, pwarps, offs, cnt, per, barid;
    if (gw < 24)      { L = 2; pbw = 0;  pwarps = 24; offs = OFF2; cnt = N2; per = 23; barid = 1; }
    else if (gw < 30) { L = 1; pbw = 24; pwarps = 6;  offs = OFF1; cnt = N1; per = 23; barid = 2; }
    else              { L = 0; pbw = 30; pwarps = 2;  offs = 0;    cnt = N0; per = 17; barid = 3; }
    int pthreads = pwarps << 5;
    int ptid = tid - (pbw << 5);

    const unsigned* sc = reinterpret_cast<const unsigned*>(g_score + b * NTOT + offs);
    unsigned v[23];
#pragma unroll
    for (int k = 0; k < 23; ++k) {
        int i = ptid + k * pthreads;
        v[k] = (k < per && i < cnt) ? __ldg(sc + i) : 0u;
    }

    if (ptid == 0) { sLo[L] = 0u; sHi[L] = 0x3F800000u; }
    NBAR(barid, pthreads);

    // tri-mid search: minimal tau with count(bits > tau) < TOPK
    for (int it = 0; it < 18; ++it) {
        unsigned lo = sLo[L], hi = sHi[L];
        unsigned c1 = 0, c2 = 0, c3 = 0, m1 = 0, m2 = 0, m3 = 0;
        if (lo < hi) {
            unsigned q = (hi - lo) >> 2;
            m1 = lo + q; m2 = m1 + q; m3 = m2 + q;
#pragma unroll
            for (int k = 0; k < 23; ++k) {
                if (k < per) {
                    c1 += (v[k] > m1) ? 1u : 0u;
                    c2 += (v[k] > m2) ? 1u : 0u;
                    c3 += (v[k] > m3) ? 1u : 0u;
                }
            }
#pragma unroll
            for (int o = 16; o; o >>= 1) {
                c1 += __shfl_down_sync(0xffffffffu, c1, o);
                c2 += __shfl_down_sync(0xffffffffu, c2, o);
                c3 += __shfl_down_sync(0xffffffffu, c3, o);
            }
        }
        if (lane == 0) { red1[gw] = c1; red2[gw] = c2; red3[gw] = c3; }
        NBAR(barid, pthreads);
        if (gw == pbw && lo < hi) {
            unsigned s1 = (lane < pwarps) ? red1[pbw + lane] : 0u;
            unsigned s2 = (lane < pwarps) ? red2[pbw + lane] : 0u;
            unsigned s3 = (lane < pwarps) ? red3[pbw + lane] : 0u;
#pragma unroll
            for (int o = 16; o; o >>= 1) {
                s1 += __shfl_down_sync(0xffffffffu, s1, o);
                s2 += __shfl_down_sync(0xffffffffu, s2, o);
                s3 += __shfl_down_sync(0xffffffffu, s3, o);
            }
            if (lane == 0) {
                if      (s1 < (unsigned)TOPK) sHi[L] = m1;
                else if (s2 < (unsigned)TOPK) { sLo[L] = m1 + 1u; sHi[L] = m2; }
                else if (s3 < (unsigned)TOPK) { sLo[L] = m2 + 1u; sHi[L] = m3; }
                else                          sLo[L] = m3 + 1u;
            }
        }
        NBAR(barid, pthreads);
    }
    unsigned tau = sLo[L];

    // partition-wide exclusive scan of strictly-greater counts
    unsigned c = 0;
#pragma unroll
    for (int k = 0; k < 23; ++k) if (k < per) c += (v[k] > tau) ? 1u : 0u;
    unsigned ws = c;
#pragma unroll
    for (int o = 1; o < 32; o <<= 1) {
        unsigned nb = __shfl_up_sync(0xffffffffu, ws, o);
        if (lane >= o) ws += nb;
    }
    if (lane == 31) red1[gw] = ws;
    NBAR(barid, pthreads);
    if (gw == pbw) {
        unsigned x = (lane < pwarps) ? red1[pbw + lane] : 0u;
#pragma unroll
        for (int o = 1; o < 32; o <<= 1) {
            unsigned nb = __shfl_up_sync(0xffffffffu, x, o);
            if (lane >= o) x += nb;
        }
        if (lane < pwarps) red1[pbw + lane] = x;
    }
    NBAR(barid, pthreads);
    unsigned excl = ((gw > pbw) ? red1[gw - 1] : 0u) + (ws - c);
    unsigned mtot = red1[pbw + pwarps - 1];

    unsigned pos = excl;
#pragma unroll
    for (int k = 0; k < 23; ++k) {
        if (k < per) {
            int i = ptid + k * pthreads;
            if (i < cnt && v[k] > tau) {
                unsigned slot = (unsigned)(L * TOPK) + pos;
                keys[slot] = ((unsigned long long)v[k] << 32)
                           | ((4095u - slot) << 15) | (unsigned)(offs + i);
                pos++;
            }
        }
    }
    NBAR(barid, pthreads);

    int r = TOPK - (int)mtot;
    int last = -1;
    for (int rep = 0; rep < r; ++rep) {
        unsigned lm = 0xFFFFFFFFu;
#pragma unroll
        for (int k = 0; k < 23; ++k) {
            if (k < per) {
                int i = ptid + k * pthreads;
                if (i < cnt && i > last && v[k] == tau) lm = min(lm, (unsigned)i);
            }
        }
#pragma unroll
        for (int o = 16; o; o >>= 1) lm = min(lm, __shfl_down_sync(0xffffffffu, lm, o));
        if (lane == 0) red2[gw] = lm;
        NBAR(barid, pthreads);
        if (gw == pbw) {
            unsigned s2 = (lane < pwarps) ? red2[pbw + lane] : 0xFFFFFFFFu;
#pragma unroll
            for (int o = 16; o; o >>= 1) s2 = min(s2, __shfl_down_sync(0xffffffffu, s2, o));
            if (lane == 0) sF[L] = s2;
        }
        NBAR(barid, pthreads);
        int found = (int)sF[L];
        if (ptid == 0 && found >= 0 && found < cnt) {
            unsigned slot = (unsigned)(L * TOPK + (int)mtot + rep);
            keys[slot] = ((unsigned long long)tau << 32)
                       | ((4095u - slot) << 15) | (unsigned)(offs + found);
        }
        last = found;
    }

    __syncthreads();   // keys[0..4095] complete

    // ======== PHASE B: bitonic sort (descending), 4 elems/thread ========
    int i0 = tid << 2;
    unsigned long long rr[4];
#pragma unroll
    for (int s = 0; s < 4; ++s) rr[s] = keys[i0 + s];
    __syncthreads();

    for (int k = 2; k <= SORTN; k <<= 1) {
        for (int j = k >> 1; j > 0; j >>= 1) {
            if (j >= 128) {
                sk[i0] = rr[0]; sk[i0 + 1] = rr[1]; sk[i0 + 2] = rr[2]; sk[i0 + 3] = rr[3];
                __syncthreads();
                int pb = i0 ^ j;
                bool takeMax = (((i0 & k) == 0) != ((i0 & j) != 0));
#pragma unroll
                for (int s = 0; s < 4; ++s) {
                    unsigned long long p = sk[pb + s];
                    rr[s] = takeMax ? u64max(rr[s], p) : u64min(rr[s], p);
                }
                __syncthreads();
            } else if (j >= 4) {
                int lx = j >> 2;
                bool takeMax = (((i0 & k) == 0) != ((i0 & j) != 0));
#pragma unroll
                for (int s = 0; s < 4; ++s) {
                    unsigned long long p = __shfl_xor_sync(0xffffffffu, rr[s], lx);
                    rr[s] = takeMax ? u64max(rr[s], p) : u64min(rr[s], p);
                }
            } else if (j == 2) {
                cswap(rr[0], rr[2], ((i0    ) & k) == 0);
                cswap(rr[1], rr[3], ((i0 + 1) & k) == 0);
            } else {
                cswap(rr[0], rr[1], ((i0    ) & k) == 0);
                cswap(rr[2], rr[3], ((i0 + 2) & k) == 0);
            }
        }
    }

    // ======== PHASE C: matrix-free chunked NMS ========
    for (int cb = 0; cb < NCAND; cb += CH) {
#pragma unroll
        for (int s = 0; s < 4; ++s) {
            int rank = i0 + s;
            if (rank >= cb && rank < cb + CH) ckey[rank - cb] = rr[s];
        }
        __syncthreads();

        int kept0 = s_kept;
        if (tid < CH) {
            unsigned long long key = ckey[tid];
            float scf = __uint_as_float((unsigned)(key >> 32));
            bool valid = (scf > MIN_SC);
            int xi1 = 0, yi1 = 0, xi2 = 0, yi2 = 0, ar = 0;
            if (valid) {
                int n = (int)((unsigned)key & 0x7FFFu);
                const float *reg, *anc;
                int local, cnt2;
                if (n < N0)        { reg = reg0; anc = anc0; local = n;        cnt2 = N0; }
                else if (n < OFF2) { reg = reg1; anc = anc1; local = n - OFF1; cnt2 = N1; }
                else               { reg = reg2; anc = anc2; local = n - OFF2; cnt2 = N2; }
                size_t base = (size_t)b * cnt2 + local;

                float4 rg = __ldg(reinterpret_cast<const float4*>(reg + base * 4));
                const float* ap = anc + base * 5;
                float ax = __ldg(ap),     ay = __ldg(ap + 1);
                float aw = __ldg(ap + 2), ah = __ldg(ap + 3);
                float st = __ldg(ap + 4);

                float cx = __fmul_rn(__fadd_rn(sigm(rg.x), ax), st);
                float cy = __fmul_rn(__fadd_rn(sigm(rg.y), ay), st);
                float w  = __fdiv_rn(__fmul_rn(expf(rg.z), aw), st);
                float h  = __fdiv_rn(__fmul_rn(expf(rg.w), ah), st);
                float x1 = __fsub_rn(cx, __fmul_rn(0.5f, w));
                float y1 = __fsub_rn(cy, __fmul_rn(0.5f, h));
                float x2 = __fadd_rn(w, x1);
                float y2 = __fadd_rn(h, y1);

                xi1 = max((int)x1, 0);
                yi1 = max((int)y1, 0);
                xi2 = min((int)x2, IMGMAX);
                yi2 = min((int)y2, IMGMAX);
                ar  = (xi2 - xi1) * (yi2 - yi1);
            }
            cx1[tid] = xi1; cy1[tid] = yi1; cx2[tid] = xi2; cy2[tid] = yi2; car[tid] = ar;

            unsigned vbal = __ballot_sync(0xffffffffu, valid);
            if ((tid & 31) == 0) limw[tid >> 5] = vbal;   // prefix mask per warp

            // kept-filter on register box (kp arrays from prior chunks are stable)
            bool sup = false;
            if (valid) {
                for (int k2 = 0; k2 < kept0; ++k2) {
                    int p1 = kp1[k2], p2 = kp2[k2];
                    int qx1 = p1 & 0xFFFF, qy1 = p1 >> 16;
                    int qx2 = p2 & 0xFFFF, qy2 = p2 >> 16;
                    int iw = min(xi2, qx2) - max(xi1, qx1);
                    int ih = min(yi2, qy2) - max(yi1, qy1);
                    if (iw > 0 && ih > 0) {
                        int inter = iw * ih;
                        if (3 * inter > ar + kar2[k2]) sup = true;
                    }
                }
            }
            unsigned sbal = __ballot_sync(0xffffffffu, sup);
            if ((tid & 31) == 0) supv[tid >> 5] = sbal;
        }
        __syncthreads();

        // warp-0 DP with on-the-fly suppression (one pass per KEPT box)
        if (tid < 32) {
            int kept = kept0;
            unsigned alive = 0u;
            if (tid < CW) alive = limw[tid] & ~supv[tid];
            while (kept < MAXDET) {
                int c2 = alive ? ((tid << 5) + __ffs(alive) - 1) : 0x7FFFFFFF;
#pragma unroll
                for (int o = 16; o; o >>= 1) c2 = min(c2, __shfl_xor_sync(0xffffffffu, c2, o));
                if (c2 == 0x7FFFFFFF) break;
                if (tid == 0) {
                    kp1[kept] = cx1[c2] | (cy1[c2] << 16);
                    kp2[kept] = cx2[c2] | (cy2[c2] << 16);
                    kar2[kept] = car[c2];
                    unsigned long long key = ckey[c2];
                    ksc[kept] = __uint_as_float((unsigned)(key >> 32));
                    kn[kept]  = (int)((unsigned)key & 0x7FFFu);
                }
                kept++;
                if (tid == (c2 >> 5)) alive &= ~(1u << (c2 & 31));
                // suppress later candidates vs the kept box (lane j-strided, conflict-free)
                int px1 = cx1[c2], py1 = cy1[c2], px2 = cx2[c2], py2 = cy2[c2], par = car[c2];
#pragma unroll
                for (int t = 0; t < CW; ++t) {
                    if ((t << 5) + 31 > c2) {          // uniform skip of earlier words
                        int j = (t << 5) + tid;
                        bool sup = false;
                        if (j > c2) {
                            int iw = min(px2, cx2[j]) - max(px1, cx1[j]);
                            int ih = min(py2, cy2[j]) - max(py1, cy1[j]);
                            if (iw > 0 && ih > 0) {
                                int inter = iw * ih;
                                if (3 * inter > par + car[j]) sup = true;
                            }
                        }
                        unsigned bal = __ballot_sync(0xffffffffu, sup);
                        if (tid == t) alive &= ~bal;
                    }
                }
                __syncwarp();
            }
            if (tid == 0) {
                s_kept = kept;
                s_done = (kept >= MAXDET) || (limw[CW - 1] != 0xFFFFFFFFu);
            }
        }
        __syncthreads();
        if (s_done) break;
        __syncthreads();
    }

    // ---- outputs (parallel) ----
    int nk = s_kept;
    const int* gcls = g_cls + b * NTOT;
    for (int k = tid; k < MAXDET; k += 1024) {
        float osc = -1.0f, ocl = -1.0f, ox1 = -1.0f, oy1 = -1.0f, ox2 = -1.0f, oy2 = -1.0f;
        if (k < nk) {
            osc = ksc[k];
            ocl = (float)__ldg(gcls + kn[k]);
            int p1 = kp1[k], p2 = kp2[k];
            ox1 = (float)(p1 & 0xFFFF); oy1 = (float)(p1 >> 16);
            ox2 = (float)(p2 & 0xFFFF); oy2 = (float)(p2 >> 16);
        }
        out[b * MAXDET + k] = osc;
        out[BATCH * MAXDET + b * MAXDET + k] = ocl;
        int ob = 2 * BATCH * MAXDET + (b * MAXDET + k) * 4;
        out[ob] = ox1; out[ob + 1] = oy1; out[ob + 2] = ox2; out[ob + 3] = oy2;
    }
}

// ---------------- launcher ----------------
extern "C" void kernel_launch(void* const* d_in, const int* in_sizes, int n_in,
                              void* d_out, int out_size)
{
    (void)out_size;
    static const int dictSizes[12] = {  8664,  34656,   693120,  43320,
                                       34656, 138624,  2772480, 173280,
                                      138624, 554496, 11089920, 693120 };
    static const int sigSizes[12]  = {  8664,  34656, 138624,
                                       34656, 138624, 554496,
                                      693120, 2772480, 11089920,
                                       43320, 173280, 693120 };
    bool isDict = (n_in >= 12), isSig = (n_in >= 12);
    for (int i = 0; i < 12 && i < n_in; i++) {
        if (in_sizes[i] != dictSizes[i]) isDict = false;
        if (in_sizes[i] != sigSizes[i])  isSig  = false;
    }

    // canonical: [0..2]=obj, [3..5]=reg, [6..8]=cls, [9..11]=anchors
    const float* in[12];
    if (isSig && !isDict) {
        for (int i = 0; i < 12; i++) in[i] = (const float*)d_in[i];
    } else {
        for (int l = 0; l < 3; l++) {
            in[l]     = (const float*)d_in[4 * l + 0];
            in[3 + l] = (const float*)d_in[4 * l + 1];
            in[6 + l] = (const float*)d_in[4 * l + 2];
            in[9 + l] = (const float*)d_in[4 * l + 3];
        }
    }

    cudaFuncSetAttribute(topk_sortnms_kernel,
                         cudaFuncAttributeMaxDynamicSharedMemorySize, DSMEM);

    int nthreads = BATCH * NTOT * 4;
    decode_kernel<<<(nthreads + 255) / 256, 256>>>(
        in[0], in[6], in[1], in[7], in[2], in[8]);

    topk_sortnms_kernel<<<BATCH, 1024, DSMEM>>>(in[3], in[9], in[4], in[10], in[5], in[11],
                                                (float*)d_out);
}

// round 14
// speedup vs baseline: 2.1422x; 2.1422x over previous
#include <cuda_runtime.h>
#include <math.h>

// ---------------- problem constants ----------------
#define NTOT   22743
#define N0     1083
#define N1     4332
#define N2     17328
#define OFF1   1083
#define OFF2   5415
#define BATCH  8
#define TOPK   1000
#define NCAND  3000
#define MAXDET 100
#define IMGMAX 607
#define SORTN  4096
#define TS     256          // NMS tile size
#define TW     8            // TS/32
#define NTILE  12           // tiles covering ranks 0..3071

// ---------------- device scratch ----------------
__device__ float g_score[BATCH * NTOT];
__device__ int4  g_box[BATCH * NTOT];
__device__ int   g_cls[BATCH * NTOT];

__device__ float g_cscore[BATCH * NCAND];
__device__ int4  g_cbox[BATCH * NCAND];
__device__ int   g_ccls[BATCH * NCAND];

__device__ unsigned long long g_skeys[BATCH * SORTN];

// matprep outputs (rank-ordered, coalesced for nms)
__device__ int4     g_nbox[BATCH * NTILE * TS];
__device__ int      g_ncls[BATCH * NTILE * TS];
__device__ unsigned g_M[BATCH * NTILE * TS * TW];

__device__ __forceinline__ float sigm(float x) { return 1.0f / (1.0f + expf(-x)); }

// ---------------- stage 1: decode (4 threads / anchor, tree-max argmax) ----------------
__global__ void decode_kernel(
    const float* __restrict__ obj0, const float* __restrict__ reg0,
    const float* __restrict__ cls0, const float* __restrict__ anc0,
    const float* __restrict__ obj1, const float* __restrict__ reg1,
    const float* __restrict__ cls1, const float* __restrict__ anc1,
    const float* __restrict__ obj2, const float* __restrict__ reg2,
    const float* __restrict__ cls2, const float* __restrict__ anc2)
{
    int t = blockIdx.x * blockDim.x + threadIdx.x;
    int a = t >> 2;
    int sub = t & 3;
    if (a >= BATCH * NTOT) a = BATCH * NTOT - 1;   // duplicates write identical data
    int b = a / NTOT;
    int n = a - b * NTOT;

    const float *obj, *reg, *cls, *anc;
    int local, cnt;
    if (n < N0)        { obj = obj0; reg = reg0; cls = cls0; anc = anc0; local = n;        cnt = N0; }
    else if (n < OFF2) { obj = obj1; reg = reg1; cls = cls1; anc = anc1; local = n - OFF1; cnt = N1; }
    else               { obj = obj2; reg = reg2; cls = cls2; anc = anc2; local = n - OFF2; cnt = N2; }

    size_t base = (size_t)b * cnt + local;

    // each of 4 threads reduces 20 classes (5 float4), tree-max + first-occurrence idx
    const float4* cp4 = reinterpret_cast<const float4*>(cls + base * 80) + sub * 5;
    float v[20];
    {
        float4 q0 = __ldg(cp4);
        float4 q1 = __ldg(cp4 + 1);
        float4 q2 = __ldg(cp4 + 2);
        float4 q3 = __ldg(cp4 + 3);
        float4 q4 = __ldg(cp4 + 4);
        v[0]=q0.x; v[1]=q0.y; v[2]=q0.z; v[3]=q0.w;
        v[4]=q1.x; v[5]=q1.y; v[6]=q1.z; v[7]=q1.w;
        v[8]=q2.x; v[9]=q2.y; v[10]=q2.z; v[11]=q2.w;
        v[12]=q3.x; v[13]=q3.y; v[14]=q3.z; v[15]=q3.w;
        v[16]=q4.x; v[17]=q4.y; v[18]=q4.z; v[19]=q4.w;
    }
    float m01 = fmaxf(v[0], v[1]),   m23 = fmaxf(v[2], v[3]);
    float m45 = fmaxf(v[4], v[5]),   m67 = fmaxf(v[6], v[7]);
    float m89 = fmaxf(v[8], v[9]),   mAB = fmaxf(v[10], v[11]);
    float mCD = fmaxf(v[12], v[13]), mEF = fmaxf(v[14], v[15]);
    float mGH = fmaxf(v[16], v[17]), mIJ = fmaxf(v[18], v[19]);
    float a0 = fmaxf(m01, m23), a1 = fmaxf(m45, m67), a2 = fmaxf(m89, mAB);
    float a3 = fmaxf(mCD, mEF), a4 = fmaxf(mGH, mIJ);
    float best = fmaxf(fmaxf(fmaxf(a0, a1), fmaxf(a2, a3)), a4);
    int bi = 19;
#pragma unroll
    for (int j = 18; j >= 0; --j) bi = (v[j] == best) ? j : bi;
    bi += sub * 20;

    // combine across the 4 sub-lanes; tie -> lower class index (first occurrence)
#pragma unroll
    for (int off = 1; off <= 2; off <<= 1) {
        float ov = __shfl_xor_sync(0xffffffffu, best, off);
        int   oi = __shfl_xor_sync(0xffffffffu, bi, off);
        if (ov > best || (ov == best && oi < bi)) { best = ov; bi = oi; }
    }

    if (sub == 0) {
        float o = sigm(__ldg(obj + base));
        float score = sigm(best) * o;

        float4 r = __ldg(reinterpret_cast<const float4*>(reg + base * 4));
        const float* ap = anc + base * 5;
        float ax = __ldg(ap),     ay = __ldg(ap + 1);
        float aw = __ldg(ap + 2), ah = __ldg(ap + 3);
        float st = __ldg(ap + 4);

        float cx = __fmul_rn(__fadd_rn(sigm(r.x), ax), st);
        float cy = __fmul_rn(__fadd_rn(sigm(r.y), ay), st);
        float w  = __fdiv_rn(__fmul_rn(expf(r.z), aw), st);
        float h  = __fdiv_rn(__fmul_rn(expf(r.w), ah), st);
        float x1 = __fsub_rn(cx, __fmul_rn(0.5f, w));
        float y1 = __fsub_rn(cy, __fmul_rn(0.5f, h));
        float x2 = __fadd_rn(w, x1);
        float y2 = __fadd_rn(h, y1);

        int xi1 = max((int)x1, 0);
        int yi1 = max((int)y1, 0);
        int xi2 = min((int)x2, IMGMAX);
        int yi2 = min((int)y2, IMGMAX);

        g_score[a] = score;
        g_box[a]   = make_int4(xi1, yi1, xi2, yi2);
        g_cls[a]   = bi;
    }
}

// ---------------- stage 2: register-cached exact top-1000 (R2-proven) ----------------
#define TKT 512
#define PER 34   // ceil(17328/512)

__global__ void __launch_bounds__(TKT) topk_kernel()
{
    int level = blockIdx.x, b = blockIdx.y;
    int offs = (level == 0) ? 0  : ((level == 1) ? OFF1 : OFF2);
    int cnt  = (level == 0) ? N0 : ((level == 1) ? N1  : N2);
    const unsigned* sc = reinterpret_cast<const unsigned*>(g_score + b * NTOT + offs);

    int tid = threadIdx.x;
    int lane = tid & 31, warp = tid >> 5;

    unsigned v[PER];
#pragma unroll
    for (int k = 0; k < PER; ++k) {
        int i = tid + (k << 9);
        v[k] = (i < cnt) ? __ldg(sc + i) : 0u;
    }

    __shared__ unsigned wred[16];
    __shared__ unsigned sb[2];
    __shared__ int s_found;
    if (tid == 0) { sb[0] = 0u; sb[1] = 0x3F800000u; }
    __syncthreads();

    unsigned lo = 0u, hi = 0x3F800000u;
    while (lo < hi) {
        unsigned mid = lo + ((hi - lo) >> 1);
        unsigned c = 0;
#pragma unroll
        for (int k = 0; k < PER; ++k) c += (v[k] > mid) ? 1u : 0u;
#pragma unroll
        for (int o = 16; o; o >>= 1) c += __shfl_down_sync(0xffffffffu, c, o);
        if (lane == 0) wred[warp] = c;
        __syncthreads();
        if (tid < 32) {
            unsigned s = (tid < 16) ? wred[tid] : 0u;
#pragma unroll
            for (int o = 8; o; o >>= 1) s += __shfl_down_sync(0xffffffffu, s, o);
            if (tid == 0) { if (s < (unsigned)TOPK) sb[1] = mid; else sb[0] = mid + 1u; }
        }
        __syncthreads();
        lo = sb[0]; hi = sb[1];
        __syncthreads();
    }
    unsigned tau = lo;

    unsigned c = 0;
#pragma unroll
    for (int k = 0; k < PER; ++k) c += (v[k] > tau) ? 1u : 0u;
    unsigned ws = c;
#pragma unroll
    for (int o = 1; o < 32; o <<= 1) {
        unsigned nb = __shfl_up_sync(0xffffffffu, ws, o);
        if (lane >= o) ws += nb;
    }
    if (lane == 31) wred[warp] = ws;
    __syncthreads();
    if (tid < 32) {
        unsigned s2 = (tid < 16) ? wred[tid] : 0u;
#pragma unroll
        for (int o = 1; o < 16; o <<= 1) {
            unsigned nb = __shfl_up_sync(0xffffffffu, s2, o);
            if (lane >= o) s2 += nb;
        }
        if (tid < 16) wred[tid] = s2;
    }
    __syncthreads();
    unsigned excl = ws - c + (warp ? wred[warp - 1] : 0u);
    unsigned mtot = wred[15];

    unsigned pos = excl;
#pragma unroll
    for (int k = 0; k < PER; ++k) {
        int i = tid + (k << 9);
        if (i < cnt && v[k] > tau) {
            int g = b * NTOT + offs + i;
            int s = b * NCAND + level * TOPK + (int)pos;
            g_cscore[s] = __uint_as_float(v[k]);
            g_cbox[s]   = g_box[g];
            g_ccls[s]   = g_cls[g];
            pos++;
        }
    }
    __syncthreads();

    int r = TOPK - (int)mtot;
    int last = -1;
    for (int rep = 0; rep < r; ++rep) {
        unsigned lm = 0xFFFFFFFFu;
#pragma unroll
        for (int k = 0; k < PER; ++k) {
            int i = tid + (k << 9);
            if (i < cnt && i > last && v[k] == tau) lm = min(lm, (unsigned)i);
        }
#pragma unroll
        for (int o = 16; o; o >>= 1) lm = min(lm, __shfl_down_sync(0xffffffffu, lm, o));
        if (lane == 0) wred[warp] = lm;
        __syncthreads();
        if (tid < 32) {
            unsigned s2 = (tid < 16) ? wred[tid] : 0xFFFFFFFFu;
#pragma unroll
            for (int o = 8; o; o >>= 1) s2 = min(s2, __shfl_down_sync(0xffffffffu, s2, o));
            if (tid == 0) s_found = (int)s2;
        }
        __syncthreads();
        int found = s_found;
        if (tid == 0 && found >= 0 && found < cnt) {
            int g = b * NTOT + offs + found;
            int s = b * NCAND + level * TOPK + (int)mtot + rep;
            g_cscore[s] = g_score[g];
            g_cbox[s]   = g_box[g];
            g_ccls[s]   = g_cls[g];
        }
        last = found;
        __syncthreads();
    }
}

// ---------------- stage 3a: bitonic sort (R2-proven) ----------------
__device__ __forceinline__ unsigned long long u64max(unsigned long long a, unsigned long long b) { return a > b ? a : b; }
__device__ __forceinline__ unsigned long long u64min(unsigned long long a, unsigned long long b) { return a < b ? a : b; }
__device__ __forceinline__ void cswap(unsigned long long& a, unsigned long long& b, bool desc)
{
    if (desc ? (a < b) : (a > b)) { unsigned long long t = a; a = b; b = t; }
}

__global__ void __launch_bounds__(1024) sort_kernel()
{
    int b = blockIdx.x;
    int t = threadIdx.x;
    int i0 = t << 2;
    __shared__ unsigned long long sk[SORTN];

    const float* cs = g_cscore + b * NCAND;
    unsigned long long r[4];
#pragma unroll
    for (int s = 0; s < 4; ++s) {
        int i = i0 + s;
        r[s] = (i < NCAND)
             ? (((unsigned long long)__float_as_uint(__ldg(cs + i)) << 32)
                | (unsigned long long)(0xFFFFFFFFu - (unsigned)i))
             : 0ull;
    }

    for (int k = 2; k <= SORTN; k <<= 1) {
        for (int j = k >> 1; j > 0; j >>= 1) {
            if (j >= 128) {
                sk[i0] = r[0]; sk[i0 + 1] = r[1]; sk[i0 + 2] = r[2]; sk[i0 + 3] = r[3];
                __syncthreads();
                int pb = i0 ^ j;
                bool takeMax = (((i0 & k) == 0) != ((i0 & j) != 0));
#pragma unroll
                for (int s = 0; s < 4; ++s) {
                    unsigned long long p = sk[pb + s];
                    r[s] = takeMax ? u64max(r[s], p) : u64min(r[s], p);
                }
                __syncthreads();
            } else if (j >= 4) {
                int lx = j >> 2;
                bool takeMax = (((i0 & k) == 0) != ((i0 & j) != 0));
#pragma unroll
                for (int s = 0; s < 4; ++s) {
                    unsigned long long p = __shfl_xor_sync(0xffffffffu, r[s], lx);
                    r[s] = takeMax ? u64max(r[s], p) : u64min(r[s], p);
                }
            } else if (j == 2) {
                cswap(r[0], r[2], ((i0    ) & k) == 0);
                cswap(r[1], r[3], ((i0 + 1) & k) == 0);
            } else {
                cswap(r[0], r[1], ((i0    ) & k) == 0);
                cswap(r[2], r[3], ((i0 + 2) & k) == 0);
            }
        }
    }

    unsigned long long* out = g_skeys + b * SORTN;
#pragma unroll
    for (int s = 0; s < 4; ++s) out[i0 + s] = r[s];
}

// ---------------- stage 3b: parallel matrix prep — grid (12 tiles, 8 images) ----------------
__global__ void __launch_bounds__(512) matprep_kernel()
{
    int t = blockIdx.x, b = blockIdx.y;
    int tid = threadIdx.x;
    int rbase = t * TS;

    __shared__ int sx1[TS], sy1[TS], sx2[TS], sy2[TS], sar[TS];

    if (tid < TS) {
        unsigned long long key = __ldg(g_skeys + b * SORTN + rbase + tid);
        unsigned slot = 0xFFFFFFFFu - (unsigned)key;
        int4 bx = make_int4(0, 0, 0, 0);
        int cl = 0;
        if (slot < (unsigned)NCAND) {
            bx = __ldg(g_cbox + b * NCAND + slot);
            cl = __ldg(g_ccls + b * NCAND + slot);
        }
        sx1[tid] = bx.x; sy1[tid] = bx.y; sx2[tid] = bx.z; sy2[tid] = bx.w;
        sar[tid] = (bx.z - bx.x) * (bx.w - bx.y);
        g_nbox[b * (NTILE * TS) + rbase + tid] = bx;
        g_ncls[b * (NTILE * TS) + rbase + tid] = cl;
    }
    __syncthreads();

    // within-tile suppression matrix (w uniform per warp -> broadcast j loads)
    for (int task = tid; task < TS * TW; task += 512) {
        int w = task >> 8;            // uniform across warp
        int i = task & (TS - 1);      // consecutive across lanes
        unsigned bits = 0u;
        int jbase = w << 5;
        if (jbase + 31 > i) {
            int x1 = sx1[i], y1 = sy1[i], x2 = sx2[i], y2 = sy2[i];
            int ar = sar[i];
#pragma unroll 8
            for (int jj = 0; jj < 32; ++jj) {
                int j = jbase + jj;
                if (j > i) {
                    int iw = min(x2, sx2[j]) - max(x1, sx1[j]);
                    int ih = min(y2, sy2[j]) - max(y1, sy1[j]);
                    if (iw > 0 && ih > 0) {
                        int inter = iw * ih;
                        // exact int equivalent of iou > 0.5
                        if (3 * inter > ar + sar[j]) bits |= (1u << jj);
                    }
                }
            }
        }
        g_M[((b * NTILE + t) * TS + i) * TW + w] = bits;
    }
}

// ---------------- stage 3c: serial NMS — loads precomputed boxes + matrices ----------------
__global__ void __launch_bounds__(1024) nms_kernel(float* __restrict__ out)
{
    int b = blockIdx.x;
    int tid = threadIdx.x;

    __shared__ int tx1[TS], ty1[TS], tx2[TS], ty2[TS], tar[TS];
    __shared__ float tsc[TS];
    __shared__ unsigned Mw[TS * TW];
    __shared__ unsigned supv[TW];
    __shared__ int kx1[MAXDET], ky1[MAXDET], kx2[MAXDET], ky2[MAXDET], kar[MAXDET];
    __shared__ int s_state[2];     // kept, done

    if (tid == 0) { s_state[0] = 0; s_state[1] = 0; }
    __syncthreads();

    const unsigned long long* keys = g_skeys + b * SORTN;
    const int4* nb = g_nbox + b * (NTILE * TS);
    const int*  nc = g_ncls + b * (NTILE * TS);

    for (int tile = 0; tile < NTILE; ++tile) {
        int rbase = tile * TS;

        // ---- coalesced tile loads ----
        if (tid < TS) {
            unsigned long long key = __ldg(keys + rbase + tid);
            tsc[tid] = __uint_as_float((unsigned)(key >> 32));
            int4 bx = __ldg(nb + rbase + tid);
            tx1[tid] = bx.x; ty1[tid] = bx.y; tx2[tid] = bx.z; ty2[tid] = bx.w;
            tar[tid] = (bx.z - bx.x) * (bx.w - bx.y);
        }
        for (int idx = tid; idx < TS * TW; idx += 1024)
            Mw[idx] = __ldg(g_M + ((b * NTILE + tile) * TS) * TW + idx);
        __syncthreads();

        // ---- suppression vs already-kept boxes (k2 uniform -> broadcast) ----
        int kept0 = s_state[0];
        if (tid < TS) {
            bool sup = false;
            int x1 = tx1[tid], y1 = ty1[tid], x2 = tx2[tid], y2 = ty2[tid], ar = tar[tid];
            for (int k2 = 0; k2 < kept0; ++k2) {
                int iw = min(x2, kx2[k2]) - max(x1, kx1[k2]);
                int ih = min(y2, ky2[k2]) - max(y1, ky1[k2]);
                if (iw > 0 && ih > 0) {
                    int inter = iw * ih;
                    if (3 * inter > ar + kar[k2]) sup = true;
                }
            }
            unsigned bal = __ballot_sync(0xffffffffu, sup);
            if ((tid & 31) == 0) supv[tid >> 5] = bal;
        }
        __syncthreads();

        // ---- warp-0 bitmask DP (R2-proven) ----
        if (tid < 32) {
            int kept = s_state[0];
            int done = 0;
            for (int g = 0; g < TW && !done; ++g) {
                int base = g << 5;
                float sc = tsc[base + tid];
                unsigned validm = __ballot_sync(0xffffffffu, sc > 0.05f);
                unsigned alive = validm & ~supv[g];
                while (alive) {
                    int bpos = __ffs(alive) - 1;
                    int i = base + bpos;
                    alive &= ~(1u << bpos);
                    if (tid == 0) {
                        kx1[kept] = tx1[i]; ky1[kept] = ty1[i];
                        kx2[kept] = tx2[i]; ky2[kept] = ty2[i];
                        kar[kept] = tar[i];
                        out[b * MAXDET + kept] = tsc[i];
                        out[BATCH * MAXDET + b * MAXDET + kept] =
                            (float)__ldg(nc + rbase + i);
                        int ob = 2 * BATCH * MAXDET + (b * MAXDET + kept) * 4;
                        out[ob]     = (float)tx1[i];
                        out[ob + 1] = (float)ty1[i];
                        out[ob + 2] = (float)tx2[i];
                        out[ob + 3] = (float)ty2[i];
                    }
                    kept++;
                    if (kept == MAXDET) { done = 1; break; }
                    alive &= ~Mw[i * TW + g];
                    if (tid < TW) supv[tid] |= Mw[i * TW + tid];
                    __syncwarp();
                }
                if (validm != 0xFFFFFFFFu) done = 1;
            }
            if (tid == 0) { s_state[0] = kept; s_state[1] = done; }
        }
        __syncthreads();
        if (s_state[1]) break;
        __syncthreads();
    }

    // ---- pad unfilled slots ----
    int kept = s_state[0];
    for (int i = kept + tid; i < MAXDET; i += 1024) {
        out[b * MAXDET + i] = -1.0f;
        out[BATCH * MAXDET + b * MAXDET + i] = -1.0f;
        int ob = 2 * BATCH * MAXDET + (b * MAXDET + i) * 4;
        out[ob] = -1.0f; out[ob + 1] = -1.0f; out[ob + 2] = -1.0f; out[ob + 3] = -1.0f;
    }
}

// ---------------- launcher ----------------
extern "C" void kernel_launch(void* const* d_in, const int* in_sizes, int n_in,
                              void* d_out, int out_size)
{
    (void)out_size;
    static const int dictSizes[12] = {  8664,  34656,   693120,  43320,
                                       34656, 138624,  2772480, 173280,
                                      138624, 554496, 11089920, 693120 };
    static const int sigSizes[12]  = {  8664,  34656, 138624,
                                       34656, 138624, 554496,
                                      693120, 2772480, 11089920,
                                       43320, 173280, 693120 };
    bool isDict = (n_in >= 12), isSig = (n_in >= 12);
    for (int i = 0; i < 12 && i < n_in; i++) {
        if (in_sizes[i] != dictSizes[i]) isDict = false;
        if (in_sizes[i] != sigSizes[i])  isSig  = false;
    }

    // canonical: [0..2]=obj, [3..5]=reg, [6..8]=cls, [9..11]=anchors
    const float* in[12];
    if (isSig && !isDict) {
        for (int i = 0; i < 12; i++) in[i] = (const float*)d_in[i];
    } else {
        for (int l = 0; l < 3; l++) {
            in[l]     = (const float*)d_in[4 * l + 0];
            in[3 + l] = (const float*)d_in[4 * l + 1];
            in[6 + l] = (const float*)d_in[4 * l + 2];
            in[9 + l] = (const float*)d_in[4 * l + 3];
        }
    }

    int nthreads = BATCH * NTOT * 4;
    decode_kernel<<<(nthreads + 255) / 256, 256>>>(
        in[0], in[3], in[6], in[9],
        in[1], in[4], in[7], in[10],
        in[2], in[5], in[8], in[11]);

    dim3 g2(3, BATCH);
    topk_kernel<<<g2, TKT>>>();

    sort_kernel<<<BATCH, 1024>>>();

    dim3 g3(NTILE, BATCH);
    matprep_kernel<<<g3, 512>>>();

    nms_kernel<<<BATCH, 1024>>>((float*)d_out);
}